// round 5
// baseline (speedup 1.0000x reference)
#include <cuda_runtime.h>

// LDDMM variational shooting RHS, Gaussian kernel sigma=0.1.
//   p      = clamp(mom, -1, 1)
//   K_ij   = exp(-50 * |x_i - x_j|^2)
//   dcp_i  = sum_j K_ij * p_j
//   dmom_i = 100 * sum_j K_ij * (p_i . p_j) * (x_i - x_j)
// Output: [dmom (N*3) | dcp (N*3)]

#define NMAX    8192
#define JSPLIT  16
#define JCHUNK  (NMAX / JSPLIT)   // 512
#define TPB     256

// -50 / ln(2)  (for ex2)
#define C_EXP2  (-72.13475204444817f)

__device__ float g_part_dmom[JSPLIT * NMAX * 3];
__device__ float g_part_dcp [JSPLIT * NMAX * 3];

__device__ __forceinline__ float ex2_approx(float a) {
    float r;
    asm("ex2.approx.ftz.f32 %0, %1;" : "=f"(r) : "f"(a));
    return r;
}

__global__ __launch_bounds__(TPB)
void lddmm_pair_kernel(const float* __restrict__ mom,
                       const float* __restrict__ x,
                       int N)
{
    // smem tile: per j, two float4: (x0,x1,x2,p0) and (p1,p2,_,_)
    __shared__ float4 s[JCHUNK * 2];

    const int i  = blockIdx.x * TPB + threadIdx.x;
    const int jc = blockIdx.y;
    const int j0 = jc * JCHUNK;

    // cooperative tile load (broadcast-read later, layout irrelevant for conflicts)
    for (int t = threadIdx.x; t < JCHUNK; t += TPB) {
        const int j = j0 + t;
        float x0 = x[3*j + 0], x1 = x[3*j + 1], x2 = x[3*j + 2];
        float p0 = mom[3*j + 0], p1 = mom[3*j + 1], p2 = mom[3*j + 2];
        p0 = fminf(fmaxf(p0, -1.0f), 1.0f);
        p1 = fminf(fmaxf(p1, -1.0f), 1.0f);
        p2 = fminf(fmaxf(p2, -1.0f), 1.0f);
        s[2*t + 0] = make_float4(x0, x1, x2, p0);
        s[2*t + 1] = make_float4(p1, p2, 0.0f, 0.0f);
    }
    __syncthreads();

    if (i >= N) return;

    const float xi0 = x[3*i + 0], xi1 = x[3*i + 1], xi2 = x[3*i + 2];
    float pi0 = mom[3*i + 0], pi1 = mom[3*i + 1], pi2 = mom[3*i + 2];
    pi0 = fminf(fmaxf(pi0, -1.0f), 1.0f);
    pi1 = fminf(fmaxf(pi1, -1.0f), 1.0f);
    pi2 = fminf(fmaxf(pi2, -1.0f), 1.0f);

    float am0 = 0.0f, am1 = 0.0f, am2 = 0.0f;   // dmom accumulator (pre-scale)
    float ac0 = 0.0f, ac1 = 0.0f, ac2 = 0.0f;   // dcp accumulator

    #pragma unroll 8
    for (int t = 0; t < JCHUNK; ++t) {
        const float4 a = s[2*t + 0];   // xj0,xj1,xj2,pj0
        const float4 b = s[2*t + 1];   // pj1,pj2,-,-

        const float dx0 = xi0 - a.x;
        const float dx1 = xi1 - a.y;
        const float dx2 = xi2 - a.z;
        const float d2  = fmaf(dx0, dx0, fmaf(dx1, dx1, dx2 * dx2));

        const float K = ex2_approx(C_EXP2 * d2);

        const float pdot = fmaf(pi0, a.w, fmaf(pi1, b.x, pi2 * b.y));

        ac0 = fmaf(K, a.w, ac0);
        ac1 = fmaf(K, b.x, ac1);
        ac2 = fmaf(K, b.y, ac2);

        const float w = K * pdot;
        am0 = fmaf(w, dx0, am0);
        am1 = fmaf(w, dx1, am1);
        am2 = fmaf(w, dx2, am2);
    }

    const int base = (jc * N + i) * 3;
    g_part_dmom[base + 0] = 100.0f * am0;
    g_part_dmom[base + 1] = 100.0f * am1;
    g_part_dmom[base + 2] = 100.0f * am2;
    g_part_dcp [base + 0] = ac0;
    g_part_dcp [base + 1] = ac1;
    g_part_dcp [base + 2] = ac2;
}

__global__ void lddmm_reduce_kernel(float* __restrict__ out, int N)
{
    const int idx = blockIdx.x * blockDim.x + threadIdx.x;  // 0 .. 3N-1
    if (idx >= 3 * N) return;

    float sm = 0.0f, sc = 0.0f;
    #pragma unroll
    for (int k = 0; k < JSPLIT; ++k) {
        sm += g_part_dmom[k * N * 3 + idx];
        sc += g_part_dcp [k * N * 3 + idx];
    }
    out[idx]         = sm;   // dmom block
    out[3 * N + idx] = sc;   // dcp block
}

extern "C" void kernel_launch(void* const* d_in, const int* in_sizes, int n_in,
                              void* d_out, int out_size)
{
    const float* mom = (const float*)d_in[0];
    const float* x   = (const float*)d_in[1];
    float* out = (float*)d_out;

    const int N = in_sizes[1] / 3;   // 8192

    dim3 grid((N + TPB - 1) / TPB, JSPLIT);
    lddmm_pair_kernel<<<grid, TPB>>>(mom, x, N);

    const int rthreads = 256;
    const int rblocks  = (3 * N + rthreads - 1) / rthreads;
    lddmm_reduce_kernel<<<rblocks, rthreads>>>(out, N);
}

// round 7
// speedup vs baseline: 1.0554x; 1.0554x over previous
#include <cuda_runtime.h>

// LDDMM variational shooting RHS, Gaussian kernel sigma=0.1, N=8192, D=3.
//   p      = clamp(mom, -1, 1)
//   K_ij   = exp(-50 * |x_i - x_j|^2)
//   dcp_i  = sum_j K_ij * p_j
//   dmom_i = 100 * sum_j K_ij * (p_i . p_j) * (x_i - x_j)
// Output: [dmom (N*3) | dcp (N*3)]
//
// Optimization: centered expansion  d2 = si + sj - 2 ci.cj  (c = x - 0.5),
// per-i exponent factor 2^(C*si) hoisted out of the loop (centering keeps the
// in-loop exponent < 128 so ex2 never overflows), rowsum form for dmom, and
// fma.rn.f32x2 packed math (2 j-points per lane iteration).

#define NMAX    8192
#define JSPLIT  16
#define JCHUNK  (NMAX / JSPLIT)   // 512
#define JPAIRS  (JCHUNK / 2)      // 256
#define TPB     256

#define C_EXP2  (-72.13475204444817f)   // -50 / ln(2)
#define B_COEF  (144.26950408889634f)   // -2 * C_EXP2
#define CENTER  0.5f

typedef unsigned long long u64;

__device__ float g_part_dmom[JSPLIT * NMAX * 3];
__device__ float g_part_dcp [JSPLIT * NMAX * 3];

__device__ __forceinline__ float ex2_approx(float a) {
    float r;
    asm("ex2.approx.ftz.f32 %0, %1;" : "=f"(r) : "f"(a));
    return r;
}
__device__ __forceinline__ u64 fma2(u64 a, u64 b, u64 c) {
    u64 d;
    asm("fma.rn.f32x2 %0, %1, %2, %3;" : "=l"(d) : "l"(a), "l"(b), "l"(c));
    return d;
}
__device__ __forceinline__ u64 mul2(u64 a, u64 b) {
    u64 d;
    asm("mul.rn.f32x2 %0, %1, %2;" : "=l"(d) : "l"(a), "l"(b));
    return d;
}
__device__ __forceinline__ u64 add2(u64 a, u64 b) {
    u64 d;
    asm("add.rn.f32x2 %0, %1, %2;" : "=l"(d) : "l"(a), "l"(b));
    return d;
}
__device__ __forceinline__ u64 pack2(float lo, float hi) {
    u64 r;
    asm("mov.b64 %0, {%1, %2};" : "=l"(r) : "f"(lo), "f"(hi));
    return r;
}
__device__ __forceinline__ float2 unpack2(u64 v) {
    float2 r;
    asm("mov.b64 {%0, %1}, %2;" : "=f"(r.x), "=f"(r.y) : "l"(v));
    return r;
}
__device__ __forceinline__ float hsum2(u64 v) {
    float2 t = unpack2(v);
    return t.x + t.y;
}

__global__ __launch_bounds__(TPB)
void lddmm_pair_kernel(const float* __restrict__ mom,
                       const float* __restrict__ x,
                       int N)
{
    // Tile layout per j-pair slot (16 floats = 4 float4):
    //   [cx0A cx0B cx1A cx1B][cx2A cx2B AjA AjB][p0A p0B p1A p1B][p2A p2B - -]
    __shared__ float4 s[JPAIRS * 4];

    const int i  = blockIdx.x * TPB + threadIdx.x;
    const int jc = blockIdx.y;
    const int j0 = jc * JCHUNK;

    {
        float* sf = (float*)s;
        for (int t = threadIdx.x; t < JCHUNK; t += TPB) {
            const int j = j0 + t;
            const float c0 = x[3*j + 0] - CENTER;
            const float c1 = x[3*j + 1] - CENTER;
            const float c2 = x[3*j + 2] - CENTER;
            const float Aj = C_EXP2 * fmaf(c0, c0, fmaf(c1, c1, c2 * c2));
            float p0 = mom[3*j + 0], p1 = mom[3*j + 1], p2 = mom[3*j + 2];
            p0 = fminf(fmaxf(p0, -1.0f), 1.0f);
            p1 = fminf(fmaxf(p1, -1.0f), 1.0f);
            p2 = fminf(fmaxf(p2, -1.0f), 1.0f);
            const int base = (t >> 1) * 16;
            const int h    = t & 1;
            sf[base +  0 + h] = c0;
            sf[base +  2 + h] = c1;
            sf[base +  4 + h] = c2;
            sf[base +  6 + h] = Aj;
            sf[base +  8 + h] = p0;
            sf[base + 10 + h] = p1;
            sf[base + 12 + h] = p2;
        }
    }
    __syncthreads();

    if (i >= N) return;

    const float ci0 = x[3*i + 0] - CENTER;
    const float ci1 = x[3*i + 1] - CENTER;
    const float ci2 = x[3*i + 2] - CENTER;
    const float si  = fmaf(ci0, ci0, fmaf(ci1, ci1, ci2 * ci2));
    float pi0 = mom[3*i + 0], pi1 = mom[3*i + 1], pi2 = mom[3*i + 2];
    pi0 = fminf(fmaxf(pi0, -1.0f), 1.0f);
    pi1 = fminf(fmaxf(pi1, -1.0f), 1.0f);
    pi2 = fminf(fmaxf(pi2, -1.0f), 1.0f);

    // Replicated i-side packed operands
    const u64 bx0 = pack2(B_COEF * ci0, B_COEF * ci0);
    const u64 bx1 = pack2(B_COEF * ci1, B_COEF * ci1);
    const u64 bx2 = pack2(B_COEF * ci2, B_COEF * ci2);
    const u64 qi0 = pack2(pi0, pi0);
    const u64 qi1 = pack2(pi1, pi1);
    const u64 qi2 = pack2(pi2, pi2);

    u64 ac0 = 0ull, ac1 = 0ull, ac2 = 0ull;   // sum K'*pj   (dcp, unscaled)
    u64 S   = 0ull;                            // sum w'
    u64 t0  = 0ull, t1  = 0ull, t2  = 0ull;   // sum w'*cxj

    #pragma unroll 4
    for (int t = 0; t < JPAIRS; ++t) {
        const float4 f0 = s[4*t + 0];
        const float4 f1 = s[4*t + 1];
        const float4 f2 = s[4*t + 2];
        const float4 f3 = s[4*t + 3];

        const u64 xj0 = pack2(f0.x, f0.y);
        const u64 xj1 = pack2(f0.z, f0.w);
        const u64 xj2 = pack2(f1.x, f1.y);
        const u64 Aj  = pack2(f1.z, f1.w);
        const u64 pj0 = pack2(f2.x, f2.y);
        const u64 pj1 = pack2(f2.z, f2.w);
        const u64 pj2 = pack2(f3.x, f3.y);

        // arg' = C*sj + B*(ci . cj);  true exponent = arg' + C*si (applied at end)
        u64 arg = fma2(bx2, xj2, Aj);
        arg = fma2(bx1, xj1, arg);
        arg = fma2(bx0, xj0, arg);

        const float2 a = unpack2(arg);
        const u64 K = pack2(ex2_approx(a.x), ex2_approx(a.y));

        u64 pd = mul2(qi2, pj2);
        pd = fma2(qi1, pj1, pd);
        pd = fma2(qi0, pj0, pd);

        ac0 = fma2(K, pj0, ac0);
        ac1 = fma2(K, pj1, ac1);
        ac2 = fma2(K, pj2, ac2);

        const u64 w = mul2(K, pd);
        S  = add2(S, w);
        t0 = fma2(w, xj0, t0);
        t1 = fma2(w, xj1, t1);
        t2 = fma2(w, xj2, t2);
    }

    const float scale = ex2_approx(C_EXP2 * si);   // 2^(C*si), <= 1
    const float Sf  = hsum2(S);
    const float tf0 = hsum2(t0), tf1 = hsum2(t1), tf2 = hsum2(t2);
    const float af0 = hsum2(ac0), af1 = hsum2(ac1), af2 = hsum2(ac2);

    const float ms = 100.0f * scale;
    const int base = (jc * N + i) * 3;
    g_part_dmom[base + 0] = ms * (ci0 * Sf - tf0);
    g_part_dmom[base + 1] = ms * (ci1 * Sf - tf1);
    g_part_dmom[base + 2] = ms * (ci2 * Sf - tf2);
    g_part_dcp [base + 0] = scale * af0;
    g_part_dcp [base + 1] = scale * af1;
    g_part_dcp [base + 2] = scale * af2;
}

__global__ void lddmm_reduce_kernel(float* __restrict__ out, int N)
{
    // 3N floats per half, processed as float4 (3N % 4 == 0 for N=8192)
    const int nvec = (3 * N) / 4;
    const int v = blockIdx.x * blockDim.x + threadIdx.x;
    if (v >= nvec) return;

    float4 sm = make_float4(0.f, 0.f, 0.f, 0.f);
    float4 sc = make_float4(0.f, 0.f, 0.f, 0.f);
    #pragma unroll
    for (int k = 0; k < JSPLIT; ++k) {
        const float4 a = ((const float4*)(g_part_dmom + k * N * 3))[v];
        const float4 b = ((const float4*)(g_part_dcp  + k * N * 3))[v];
        sm.x += a.x; sm.y += a.y; sm.z += a.z; sm.w += a.w;
        sc.x += b.x; sc.y += b.y; sc.z += b.z; sc.w += b.w;
    }
    ((float4*)out)[v]        = sm;   // dmom block
    ((float4*)out)[nvec + v] = sc;   // dcp block
}

extern "C" void kernel_launch(void* const* d_in, const int* in_sizes, int n_in,
                              void* d_out, int out_size)
{
    const float* mom = (const float*)d_in[0];
    const float* x   = (const float*)d_in[1];
    float* out = (float*)d_out;

    const int N = in_sizes[1] / 3;   // 8192

    dim3 grid((N + TPB - 1) / TPB, JSPLIT);
    lddmm_pair_kernel<<<grid, TPB>>>(mom, x, N);

    const int nvec = (3 * N) / 4;
    const int rthreads = 256;
    const int rblocks  = (nvec + rthreads - 1) / rthreads;
    lddmm_reduce_kernel<<<rblocks, rthreads>>>(out, N);
}

// round 8
// speedup vs baseline: 1.1325x; 1.0731x over previous
#include <cuda_runtime.h>

// LDDMM variational shooting RHS, Gaussian kernel sigma=0.1, N=8192, D=3.
//   p      = clamp(mom, -1, 1)
//   K_ij   = exp(-50 * |x_i - x_j|^2)
//   dcp_i  = sum_j K_ij * p_j
//   dmom_i = 100 * sum_j K_ij * (p_i . p_j) * (x_i - x_j)
// Output: [dmom (N*3) | dcp (N*3)]
//
// R8: smem tile stored as f32x2 (u64) values -> ld.shared.v2.b64 feeds
// fma.rn.f32x2 with aligned register pairs, zero pack MOVs in the hot loop.
// Centered expansion with hoisted per-i exponent factor (see R6 notes).

#define NMAX    8192
#define JSPLIT  16
#define JCHUNK  (NMAX / JSPLIT)   // 512
#define JPAIRS  (JCHUNK / 2)      // 256
#define TPB     256

#define C_EXP2  (-72.13475204444817f)   // -50 / ln(2)
#define B_COEF  (144.26950408889634f)   // -2 * C_EXP2
#define CENTER  0.5f

typedef unsigned long long u64;

__device__ float g_part_dmom[JSPLIT * NMAX * 3];
__device__ float g_part_dcp [JSPLIT * NMAX * 3];

__device__ __forceinline__ float ex2_approx(float a) {
    float r;
    asm("ex2.approx.ftz.f32 %0, %1;" : "=f"(r) : "f"(a));
    return r;
}
__device__ __forceinline__ u64 fma2(u64 a, u64 b, u64 c) {
    u64 d;
    asm("fma.rn.f32x2 %0, %1, %2, %3;" : "=l"(d) : "l"(a), "l"(b), "l"(c));
    return d;
}
__device__ __forceinline__ u64 mul2(u64 a, u64 b) {
    u64 d;
    asm("mul.rn.f32x2 %0, %1, %2;" : "=l"(d) : "l"(a), "l"(b));
    return d;
}
__device__ __forceinline__ u64 add2(u64 a, u64 b) {
    u64 d;
    asm("add.rn.f32x2 %0, %1, %2;" : "=l"(d) : "l"(a), "l"(b));
    return d;
}
__device__ __forceinline__ u64 pack2(float lo, float hi) {
    u64 r;
    asm("mov.b64 %0, {%1, %2};" : "=l"(r) : "f"(lo), "f"(hi));
    return r;
}
__device__ __forceinline__ float2 unpack2(u64 v) {
    float2 r;
    asm("mov.b64 {%0, %1}, %2;" : "=f"(r.x), "=f"(r.y) : "l"(v));
    return r;
}
__device__ __forceinline__ float hsum2(u64 v) {
    float2 t = unpack2(v);
    return t.x + t.y;
}

__global__ __launch_bounds__(TPB)
void lddmm_pair_kernel(const float* __restrict__ mom,
                       const float* __restrict__ x,
                       int N)
{
    // Per j-pair slot: 8 u64 (f32x2) = [xj0 xj1 | xj2 Aj | pj0 pj1 | pj2 pad]
    __shared__ __align__(16) u64 s[JPAIRS * 8];

    const int i  = blockIdx.x * TPB + threadIdx.x;
    const int jc = blockIdx.y;
    const int j0 = jc * JCHUNK;

    {
        float* sf = (float*)s;
        for (int t = threadIdx.x; t < JCHUNK; t += TPB) {
            const int j = j0 + t;
            const float c0 = x[3*j + 0] - CENTER;
            const float c1 = x[3*j + 1] - CENTER;
            const float c2 = x[3*j + 2] - CENTER;
            const float Aj = C_EXP2 * fmaf(c0, c0, fmaf(c1, c1, c2 * c2));
            float p0 = mom[3*j + 0], p1 = mom[3*j + 1], p2 = mom[3*j + 2];
            p0 = fminf(fmaxf(p0, -1.0f), 1.0f);
            p1 = fminf(fmaxf(p1, -1.0f), 1.0f);
            p2 = fminf(fmaxf(p2, -1.0f), 1.0f);
            const int base = (t >> 1) * 16;   // floats per pair-slot
            const int h    = t & 1;
            sf[base +  0 + h] = c0;   // xj0 lanes
            sf[base +  2 + h] = c1;   // xj1
            sf[base +  4 + h] = c2;   // xj2
            sf[base +  6 + h] = Aj;   // Aj
            sf[base +  8 + h] = p0;   // pj0
            sf[base + 10 + h] = p1;   // pj1
            sf[base + 12 + h] = p2;   // pj2
            sf[base + 14 + h] = 0.0f; // pad
        }
    }
    __syncthreads();

    if (i >= N) return;

    const float ci0 = x[3*i + 0] - CENTER;
    const float ci1 = x[3*i + 1] - CENTER;
    const float ci2 = x[3*i + 2] - CENTER;
    const float si  = fmaf(ci0, ci0, fmaf(ci1, ci1, ci2 * ci2));
    float pi0 = mom[3*i + 0], pi1 = mom[3*i + 1], pi2 = mom[3*i + 2];
    pi0 = fminf(fmaxf(pi0, -1.0f), 1.0f);
    pi1 = fminf(fmaxf(pi1, -1.0f), 1.0f);
    pi2 = fminf(fmaxf(pi2, -1.0f), 1.0f);

    // Replicated i-side packed operands (packed once, outside the loop)
    const u64 bx0 = pack2(B_COEF * ci0, B_COEF * ci0);
    const u64 bx1 = pack2(B_COEF * ci1, B_COEF * ci1);
    const u64 bx2 = pack2(B_COEF * ci2, B_COEF * ci2);
    const u64 qi0 = pack2(pi0, pi0);
    const u64 qi1 = pack2(pi1, pi1);
    const u64 qi2 = pack2(pi2, pi2);

    u64 ac0 = 0ull, ac1 = 0ull, ac2 = 0ull;   // sum K'*pj
    u64 S   = 0ull;                            // sum w'
    u64 t0  = 0ull, t1  = 0ull, t2  = 0ull;   // sum w'*cxj

    const ulonglong2* sp = (const ulonglong2*)s;

    #pragma unroll 8
    for (int t = 0; t < JPAIRS; ++t) {
        const ulonglong2 q0 = sp[4*t + 0];   // xj0, xj1
        const ulonglong2 q1 = sp[4*t + 1];   // xj2, Aj
        const ulonglong2 q2 = sp[4*t + 2];   // pj0, pj1
        const ulonglong2 q3 = sp[4*t + 3];   // pj2, pad

        // arg' = Aj + B*(ci . cj);  true exponent = arg' + C*si (applied at end)
        u64 arg = fma2(bx2, q1.x, q1.y);
        arg = fma2(bx1, q0.y, arg);
        arg = fma2(bx0, q0.x, arg);

        const float2 a = unpack2(arg);
        const u64 K = pack2(ex2_approx(a.x), ex2_approx(a.y));

        u64 pd = mul2(qi2, q3.x);
        pd = fma2(qi1, q2.y, pd);
        pd = fma2(qi0, q2.x, pd);

        ac0 = fma2(K, q2.x, ac0);
        ac1 = fma2(K, q2.y, ac1);
        ac2 = fma2(K, q3.x, ac2);

        const u64 w = mul2(K, pd);
        S  = add2(S, w);
        t0 = fma2(w, q0.x, t0);
        t1 = fma2(w, q0.y, t1);
        t2 = fma2(w, q1.x, t2);
    }

    const float scale = ex2_approx(C_EXP2 * si);   // 2^(C*si) <= 1
    const float Sf  = hsum2(S);
    const float tf0 = hsum2(t0), tf1 = hsum2(t1), tf2 = hsum2(t2);
    const float af0 = hsum2(ac0), af1 = hsum2(ac1), af2 = hsum2(ac2);

    const float ms = 100.0f * scale;
    const int base = (jc * N + i) * 3;
    g_part_dmom[base + 0] = ms * (ci0 * Sf - tf0);
    g_part_dmom[base + 1] = ms * (ci1 * Sf - tf1);
    g_part_dmom[base + 2] = ms * (ci2 * Sf - tf2);
    g_part_dcp [base + 0] = scale * af0;
    g_part_dcp [base + 1] = scale * af1;
    g_part_dcp [base + 2] = scale * af2;
}

__global__ void lddmm_reduce_kernel(float* __restrict__ out, int N)
{
    // 6N threads: idx < 3N -> dmom half, else dcp half. More blocks = more MLP.
    const int idx = blockIdx.x * blockDim.x + threadIdx.x;
    const int n3  = 3 * N;
    if (idx >= 2 * n3) return;

    const int e = (idx < n3) ? idx : (idx - n3);
    const float* src = (idx < n3) ? g_part_dmom : g_part_dcp;

    float sum = 0.0f;
    #pragma unroll
    for (int k = 0; k < JSPLIT; ++k)
        sum += __ldg(src + k * n3 + e);
    out[idx] = sum;
}

extern "C" void kernel_launch(void* const* d_in, const int* in_sizes, int n_in,
                              void* d_out, int out_size)
{
    const float* mom = (const float*)d_in[0];
    const float* x   = (const float*)d_in[1];
    float* out = (float*)d_out;

    const int N = in_sizes[1] / 3;   // 8192

    dim3 grid((N + TPB - 1) / TPB, JSPLIT);
    lddmm_pair_kernel<<<grid, TPB>>>(mom, x, N);

    const int rthreads = 256;
    const int rblocks  = (6 * N + rthreads - 1) / rthreads;
    lddmm_reduce_kernel<<<rblocks, rthreads>>>(out, N);
}